// round 9
// baseline (speedup 1.0000x reference)
#include <cuda_runtime.h>
#include <cuda_bf16.h>
#include <cstdint>

// Problem constants
#define NPRED 600
#define T     60
#define C     91
#define HW    65536
#define MROWS 1280          // 640 s-rows + 640 d-rows
#define TPAD  64
#define KSLICES 32
#define KLOC  2048          // K pixels per slice
#define NCHUNK 32           // chunks of 64 px
#define TSEG  8

// ---- fused-kernel smem layout (dynamic) ----
#define RAWPITCH 272                    // 256B row + 16B pad
#define RAWSTAGE (64 * RAWPITCH)        // 17408, 3 slots
#define AT_OFF   (3 * RAWSTAGE)         // 52224, A-tile 128x128B, 2 slots
#define B_OFF    (AT_OFF + 2 * 16384)   // 84992, B 64x128B, 3 slots
#define FUSED_SMEM (B_OFF + 3 * 8192)   // 109568

// swizzle for 8-granule (128B) rows
#define SWZ8(r, g) (((g) ^ (r)) & 7)

// named barrier ids: full = 1 + (c&1), free = 3 + (c&1)
#define BAR_ARRIVE(id) asm volatile("bar.arrive %0, 256;" :: "r"(id) : "memory")
#define BAR_SYNC(id)   asm volatile("bar.sync %0, 256;"   :: "r"(id) : "memory")

// ---------------- scratch (static device globals; no allocation) -------------
__device__ __nv_bfloat16 g_B[(size_t)TPAD * HW];            // 8 MB; rows 60..63 stay 0
__device__ float g_part[(size_t)KSLICES * MROWS * TPAD];    // 10.5 MB GEMM partials
__device__ float g_ab[(size_t)MROWS * TPAD];
__device__ float g_spart[(size_t)KSLICES * 640 * 8];        // pred stat partials
__device__ float g_tpart[(size_t)TSEG * T * 8];             // tgt stat partials
__device__ float g_pstats[NPRED * 8];
__device__ float g_tstats[T * 8];

// ---------------- PTX helpers (plain-sm_100 legal) ----------------------------
__device__ __forceinline__ void ldsm4(uint32_t& r0, uint32_t& r1, uint32_t& r2,
                                      uint32_t& r3, uint32_t addr) {
    asm volatile("ldmatrix.sync.aligned.m8n8.x4.shared.b16 {%0,%1,%2,%3}, [%4];"
                 : "=r"(r0), "=r"(r1), "=r"(r2), "=r"(r3) : "r"(addr));
}
__device__ __forceinline__ void mma16816(float* c, uint32_t a0, uint32_t a1,
                                         uint32_t a2, uint32_t a3,
                                         uint32_t b0, uint32_t b1) {
    asm volatile(
        "mma.sync.aligned.m16n8k16.row.col.f32.bf16.bf16.f32 "
        "{%0,%1,%2,%3}, {%4,%5,%6,%7}, {%8,%9}, {%0,%1,%2,%3};"
        : "+f"(c[0]), "+f"(c[1]), "+f"(c[2]), "+f"(c[3])
        : "r"(a0), "r"(a1), "r"(a2), "r"(a3), "r"(b0), "r"(b1));
}
#define CPA16(dst, src) \
    asm volatile("cp.async.cg.shared.global [%0], [%1], 16;" :: "r"(dst), "l"(src))
#define CP_COMMIT() asm volatile("cp.async.commit_group;" ::: "memory")

// ---------------- block reduction helpers ------------------------------------
__device__ __forceinline__ float blk_reduce_sum(float v, float* sh) {
    int tid = threadIdx.x;
    sh[tid] = v; __syncthreads();
    for (int s = 128; s > 0; s >>= 1) {
        if (tid < s) sh[tid] += sh[tid + s];
        __syncthreads();
    }
    float r = sh[0]; __syncthreads();
    return r;
}
__device__ __forceinline__ float blk_reduce_max(float v, float* sh) {
    int tid = threadIdx.x;
    sh[tid] = v; __syncthreads();
    for (int s = 128; s > 0; s >>= 1) {
        if (tid < s) sh[tid] = fmaxf(sh[tid], sh[tid + s]);
        __syncthreads();
    }
    float r = sh[0]; __syncthreads();
    return r;
}
__device__ __forceinline__ float blk_reduce_min(float v, float* sh) {
    int tid = threadIdx.x;
    sh[tid] = v; __syncthreads();
    for (int s = 128; s > 0; s >>= 1) {
        if (tid < s) sh[tid] = fminf(sh[tid], sh[tid + s]);
        __syncthreads();
    }
    float r = sh[0]; __syncthreads();
    return r;
}

// ---------------- K1: target stats + bf16 B matrix (segmented) ---------------
__global__ void tgt_kernel(const int* __restrict__ tmasks) {
    __shared__ float sh[256];
    int t = blockIdx.x, seg = blockIdx.y, tid = threadIdx.x;
    const int4* row = (const int4*)(tmasks + (size_t)t * HW + seg * 8192);
    __nv_bfloat162* brow = (__nv_bfloat162*)(g_B + (size_t)t * HW + seg * 8192);
    float xmin = 1e8f, ymin = 1e8f, xmax = -1e30f, ymax = -1e30f, ts = 0.f;
    for (int i = tid; i < 2048; i += 256) {
        int4 v = row[i];
        int px0 = seg * 8192 + i * 4;
        float mv[4] = {(float)v.x, (float)v.y, (float)v.z, (float)v.w};
        #pragma unroll
        for (int j = 0; j < 4; j++) {
            float m = mv[j];
            int px = px0 + j;
            float x = (float)(px & 255), y = (float)(px >> 8);
            float mx = m * x, my = m * y;
            xmax = fmaxf(xmax, mx);
            ymax = fmaxf(ymax, my);
            if (m != 0.f) { xmin = fminf(xmin, mx); ymin = fminf(ymin, my); }
            ts += m;
        }
        __nv_bfloat162 h0, h1;
        h0.x = __float2bfloat16_rn(mv[0]); h0.y = __float2bfloat16_rn(mv[1]);
        h1.x = __float2bfloat16_rn(mv[2]); h1.y = __float2bfloat16_rn(mv[3]);
        brow[i * 2 + 0] = h0;
        brow[i * 2 + 1] = h1;
    }
    float rxmin = blk_reduce_min(xmin, sh);
    float rymin = blk_reduce_min(ymin, sh);
    float rxmax = blk_reduce_max(xmax, sh);
    float rymax = blk_reduce_max(ymax, sh);
    float rts   = blk_reduce_sum(ts, sh);
    if (tid == 0) {
        float* o = g_tpart + ((size_t)seg * T + t) * 8;
        o[0] = rxmin; o[1] = rymin; o[2] = rxmax; o[3] = rymax; o[4] = rts;
    }
}

// ---------------- K2: warp-specialized fused kernel ---------------------------
// warps 4-7: producers (raw cp.async ring -> transform -> A-tile STS + stats)
// warps 0-3: consumers (B cp.async ring -> ldsm -> MMA -> epilogue)
__global__ void __launch_bounds__(256, 2) fused_kernel(const float* __restrict__ pmasks) {
    extern __shared__ __align__(1024) char smem[];
    uint32_t sb = (uint32_t)__cvta_generic_to_shared(smem);
    int tid = threadIdx.x, lane = tid & 31, wid = tid >> 5;
    int mtile = blockIdx.x, ksl = blockIdx.y;

    if (wid >= 4) {
        // ======================= PRODUCER =======================
        int t2 = tid - 128;
        int pr = t2 >> 1, q = t2 & 1;
        int pred = mtile * 64 + pr;
        bool valid = pred < NPRED;
        int prx = pr & 7;
        const char* aSrc = (const char*)pmasks + (size_t)pred * (HW * 4)
                           + (size_t)ksl * (KLOC * 4) + q * 128;   // + c*256 + gi*16
        uint32_t rawB = sb + (uint32_t)(pr * RAWPITCH + q * 128);
        uint32_t sRow = sb + AT_OFF + (uint32_t)(pr * 128);
        uint32_t dRow = sb + AT_OFF + (uint32_t)((64 + pr) * 128);

        // prologue: stage raw chunks 0,1
        #pragma unroll
        for (int k = 0; k < 2; k++) {
            if (valid) {
                uint32_t rd = rawB + (uint32_t)(k * RAWSTAGE);
                const char* as = aSrc + k * 256;
                #pragma unroll
                for (int gi = 0; gi < 8; gi++)
                    CPA16(rd + (uint32_t)(gi * 16), as + gi * 16);
            }
            CP_COMMIT();
        }

        float xmax = -1e30f, ymax = -1e30f, xminm = 1e8f, yminm = 1e8f;
        float ps = 0.f, ns = 0.f;

        for (int c = 0; c < NCHUNK; c++) {
            // stage raw(c+2) first (self-owned region, no barrier needed)
            if (c + 2 < NCHUNK && valid) {
                uint32_t rd = rawB + (uint32_t)(((c + 2) % 3) * RAWSTAGE);
                const char* as = aSrc + (c + 2) * 256;
                #pragma unroll
                for (int gi = 0; gi < 8; gi++)
                    CPA16(rd + (uint32_t)(gi * 16), as + gi * 16);
            }
            CP_COMMIT();

            if (c >= 2) BAR_SYNC(3 + (c & 1));             // A-tile slot free
            asm volatile("cp.async.wait_group 2;" ::: "memory");  // raw(c) resident

            uint32_t raw = rawB + (uint32_t)((c % 3) * RAWSTAGE);
            uint32_t til = (uint32_t)((c & 1) * 16384);
            float yf = (float)(ksl * 8 + (c >> 2));
            float xb = (float)((c & 3) * 64 + q * 32);
            float cmax = -1e30f, cminm = 1e8f;
            uint32_t usv[4], udv[4];
            #pragma unroll
            for (int i = 0; i < 8; i++) {
                float sj[4], dj[4];
                if (valid) {
                    float4 v;
                    asm volatile("ld.shared.v4.f32 {%0,%1,%2,%3}, [%4];"
                                 : "=f"(v.x), "=f"(v.y), "=f"(v.z), "=f"(v.w)
                                 : "r"(raw + (uint32_t)(i * 16)));
                    float mmv[4] = {v.x, v.y, v.z, v.w};
                    #pragma unroll
                    for (int j = 0; j < 4; j++) {
                        float m = mmv[j];
                        float x = xb + (float)(i * 4 + j);
                        float mx = m * x;
                        xmax = fmaxf(xmax, mx);
                        cmax = fmaxf(cmax, m);
                        if (m != 0.f) { xminm = fminf(xminm, mx); cminm = fminf(cminm, m); }
                        float ee = __expf(-m);
                        float tt = 1.f + ee;
                        float p = __fdividef(1.f, tt);
                        float qq = ee * p;                 // 1 - p
                        float lp = -__logf(tt);            // log p
                        float lq = lp - m;                 // log(1-p)
                        float pos = -0.25f * qq * qq * lp;
                        float neg = -0.75f * p * p * lq;
                        ps += p;
                        ns += neg;
                        sj[j] = p;
                        dj[j] = pos - neg;
                    }
                } else {
                    #pragma unroll
                    for (int j = 0; j < 4; j++) { sj[j] = 0.f; dj[j] = 0.f; }
                }
                __nv_bfloat162 hs0 = __floats2bfloat162_rn(sj[0], sj[1]);
                __nv_bfloat162 hs1 = __floats2bfloat162_rn(sj[2], sj[3]);
                __nv_bfloat162 hd0 = __floats2bfloat162_rn(dj[0], dj[1]);
                __nv_bfloat162 hd1 = __floats2bfloat162_rn(dj[2], dj[3]);
                int idx = (i & 1) * 2;
                usv[idx] = *(uint32_t*)&hs0; usv[idx + 1] = *(uint32_t*)&hs1;
                udv[idx] = *(uint32_t*)&hd0; udv[idx + 1] = *(uint32_t*)&hd1;
                if (i & 1) {
                    int g2 = q * 4 + (i >> 1);
                    uint32_t so = sRow + til + (uint32_t)(SWZ8(prx, g2) << 4);
                    uint32_t dofs = dRow + til + (uint32_t)(SWZ8(prx, g2) << 4);
                    asm volatile("st.shared.v4.b32 [%0], {%1,%2,%3,%4};"
                                 :: "r"(so), "r"(usv[0]), "r"(usv[1]), "r"(usv[2]), "r"(usv[3]));
                    asm volatile("st.shared.v4.b32 [%0], {%1,%2,%3,%4};"
                                 :: "r"(dofs), "r"(udv[0]), "r"(udv[1]), "r"(udv[2]), "r"(udv[3]));
                }
            }
            if (valid) {
                ymax = fmaxf(ymax, yf * cmax);
                if (cminm < 1e8f) yminm = fminf(yminm, yf * cminm);
            }
            BAR_ARRIVE(1 + (c & 1));                        // A-tile(c) full
        }

        // stats epilogue: reduce thread pair (q) via shfl
        xminm = fminf(xminm, __shfl_xor_sync(0xffffffffu, xminm, 1));
        yminm = fminf(yminm, __shfl_xor_sync(0xffffffffu, yminm, 1));
        xmax = fmaxf(xmax, __shfl_xor_sync(0xffffffffu, xmax, 1));
        ymax = fmaxf(ymax, __shfl_xor_sync(0xffffffffu, ymax, 1));
        ps += __shfl_xor_sync(0xffffffffu, ps, 1);
        ns += __shfl_xor_sync(0xffffffffu, ns, 1);
        if (q == 0) {
            float* o = g_spart + ((size_t)ksl * 640 + mtile * 64 + pr) * 8;
            o[0] = xminm; o[1] = yminm; o[2] = xmax; o[3] = ymax; o[4] = ps; o[5] = ns;
        }
    } else {
        // ======================= CONSUMER =======================
        int w = wid;
        int brow = tid >> 1, qb = tid & 1;
        int brx = brow & 7;
        const char* bSrc = (const char*)g_B + (size_t)brow * (HW * 2)
                           + (size_t)ksl * (KLOC * 2) + qb * 64;   // + c*128 + gi*16
        uint32_t bRowD = sb + B_OFF + (uint32_t)(brow * 128);

        int srow = (lane & 7) + ((lane >> 3) & 1) * 8;
        int ghi  = lane >> 4;
        int rowA0 = w * 32 + srow, rowA1 = rowA0 + 16;
        uint32_t offA0 = sb + AT_OFF + (uint32_t)(rowA0 * 128); int xa0 = rowA0 & 7;
        uint32_t offA1 = sb + AT_OFF + (uint32_t)(rowA1 * 128); int xa1 = rowA1 & 7;
        uint32_t offB[4]; int xbq[4];
        #pragma unroll
        for (int qi = 0; qi < 4; qi++) {
            int r = qi * 16 + srow;
            offB[qi] = sb + B_OFF + (uint32_t)(r * 128);
            xbq[qi] = r & 7;
        }

        // prologue: stage B chunks 0,1
        #pragma unroll
        for (int k = 0; k < 2; k++) {
            uint32_t bd = bRowD + (uint32_t)(k * 8192);
            const char* bs = bSrc + k * 128;
            #pragma unroll
            for (int gi = 0; gi < 4; gi++) {
                int g = qb * 4 + gi;
                CPA16(bd + (uint32_t)(SWZ8(brx, g) << 4), bs + gi * 16);
            }
            CP_COMMIT();
        }

        float acc[2][8][4];
        #pragma unroll
        for (int mi = 0; mi < 2; mi++)
            #pragma unroll
            for (int ni = 0; ni < 8; ni++)
                #pragma unroll
                for (int e = 0; e < 4; e++) acc[mi][ni][e] = 0.f;

        for (int c = 0; c < NCHUNK; c++) {
            asm volatile("cp.async.wait_group 1;" ::: "memory");  // B(c) (mine)
            BAR_SYNC(1 + (c & 1));            // A-tile(c) + all B(c) visible

            uint32_t atil = (uint32_t)((c & 1) * 16384);
            uint32_t btil = (uint32_t)((c % 3) * 8192);
            #pragma unroll
            for (int ks = 0; ks < 4; ks++) {
                int g = 2 * ks + ghi;
                uint32_t a0, a1, a2, a3, a4, a5, a6, a7;
                uint32_t bf[4][4];
                ldsm4(a0, a1, a2, a3, offA0 + atil + (uint32_t)(SWZ8(xa0, g) << 4));
                ldsm4(a4, a5, a6, a7, offA1 + atil + (uint32_t)(SWZ8(xa1, g) << 4));
                #pragma unroll
                for (int qi = 0; qi < 4; qi++)
                    ldsm4(bf[qi][0], bf[qi][1], bf[qi][2], bf[qi][3],
                          offB[qi] + btil + (uint32_t)(SWZ8(xbq[qi], g) << 4));
                #pragma unroll
                for (int qi = 0; qi < 4; qi++) {
                    mma16816(acc[0][2 * qi + 0], a0, a1, a2, a3, bf[qi][0], bf[qi][2]);
                    mma16816(acc[0][2 * qi + 1], a0, a1, a2, a3, bf[qi][1], bf[qi][3]);
                    mma16816(acc[1][2 * qi + 0], a4, a5, a6, a7, bf[qi][0], bf[qi][2]);
                    mma16816(acc[1][2 * qi + 1], a4, a5, a6, a7, bf[qi][1], bf[qi][3]);
                }
            }

            // stage B(c+2)
            if (c + 2 < NCHUNK) {
                uint32_t bd = bRowD + (uint32_t)(((c + 2) % 3) * 8192);
                const char* bs = bSrc + (c + 2) * 128;
                #pragma unroll
                for (int gi = 0; gi < 4; gi++) {
                    int g = qb * 4 + gi;
                    CPA16(bd + (uint32_t)(SWZ8(brx, g) << 4), bs + gi * 16);
                }
            }
            CP_COMMIT();
            BAR_ARRIVE(3 + (c & 1));          // A-tile(c) free
        }

        // GEMM epilogue
        #pragma unroll
        for (int mi = 0; mi < 2; mi++) {
            #pragma unroll
            for (int half = 0; half < 2; half++) {
                int larow = w * 32 + mi * 16 + (lane >> 2) + half * 8;
                int grow = (larow < 64) ? (mtile * 64 + larow) : (576 + mtile * 64 + larow);
                float* dst = g_part + ((size_t)ksl * MROWS + grow) * TPAD;
                #pragma unroll
                for (int ni = 0; ni < 8; ni++) {
                    int n0 = ni * 8 + (lane & 3) * 2;
                    dst[n0 + 0] = acc[mi][ni][half * 2 + 0];
                    dst[n0 + 1] = acc[mi][ni][half * 2 + 1];
                }
            }
        }
    }
}

// ---------------- K3: merged deterministic reductions -------------------------
__global__ void reduce_all() {
    if (blockIdx.x < 320) {
        int idx = blockIdx.x * 256 + threadIdx.x;
        float s = 0.f;
        #pragma unroll
        for (int k = 0; k < KSLICES; k++)
            s += g_part[(size_t)k * MROWS * TPAD + idx];
        g_ab[idx] = s;
        return;
    }
    int w = (blockIdx.x - 320) * 8 + (threadIdx.x >> 5);
    int lane = threadIdx.x & 31;
    if (w < NPRED) {
        const float* o = g_spart + ((size_t)lane * 640 + w) * 8;
        float xmin = o[0], ymin = o[1], xmax = o[2], ymax = o[3];
        float ps = o[4], ns = o[5];
        #pragma unroll
        for (int off = 16; off > 0; off >>= 1) {
            xmin = fminf(xmin, __shfl_xor_sync(0xffffffffu, xmin, off));
            ymin = fminf(ymin, __shfl_xor_sync(0xffffffffu, ymin, off));
            xmax = fmaxf(xmax, __shfl_xor_sync(0xffffffffu, xmax, off));
            ymax = fmaxf(ymax, __shfl_xor_sync(0xffffffffu, ymax, off));
            ps += __shfl_xor_sync(0xffffffffu, ps, off);
            ns += __shfl_xor_sync(0xffffffffu, ns, off);
        }
        if (lane == 0) {
            float* d = g_pstats + w * 8;
            d[0] = xmin; d[1] = ymin; d[2] = xmax; d[3] = ymax; d[4] = ps; d[5] = ns;
        }
    } else if (w < NPRED + T) {
        int t = w - NPRED;
        float xmin = 1e8f, ymin = 1e8f, xmax = -1e30f, ymax = -1e30f, ts = 0.f;
        if (lane < TSEG) {
            const float* o = g_tpart + ((size_t)lane * T + t) * 8;
            xmin = o[0]; ymin = o[1]; xmax = o[2]; ymax = o[3]; ts = o[4];
        }
        #pragma unroll
        for (int off = 4; off > 0; off >>= 1) {
            xmin = fminf(xmin, __shfl_xor_sync(0xffffffffu, xmin, off));
            ymin = fminf(ymin, __shfl_xor_sync(0xffffffffu, ymin, off));
            xmax = fmaxf(xmax, __shfl_xor_sync(0xffffffffu, xmax, off));
            ymax = fmaxf(ymax, __shfl_xor_sync(0xffffffffu, ymax, off));
            ts += __shfl_xor_sync(0xffffffffu, ts, off);
        }
        if (lane == 0) {
            float* d = g_tstats + t * 8;
            d[0] = xmin; d[1] = ymin; d[2] = xmax; d[3] = ymax; d[4] = ts;
        }
    }
}

// ---------------- K4: final cost assembly ------------------------------------
__device__ __forceinline__ float4 cxcywh_to_xyxy(float4 b) {
    return make_float4(b.x - 0.5f * b.z, b.y - 0.5f * b.w,
                       b.x + 0.5f * b.z, b.y + 0.5f * b.w);
}
__device__ __forceinline__ float giou(float4 A, float4 B) {
    float area1 = (A.z - A.x) * (A.w - A.y);
    float area2 = (B.z - B.x) * (B.w - B.y);
    float ltx = fmaxf(A.x, B.x), lty = fmaxf(A.y, B.y);
    float rbx = fminf(A.z, B.z), rby = fminf(A.w, B.w);
    float w = fmaxf(rbx - ltx, 0.f), h = fmaxf(rby - lty, 0.f);
    float inter = w * h;
    float uni = area1 + area2 - inter;
    float iou = inter / uni;
    float ex = fminf(A.x, B.x), ey = fminf(A.y, B.y);
    float ex2 = fmaxf(A.z, B.z), ey2 = fmaxf(A.w, B.w);
    float we = fmaxf(ex2 - ex, 0.f), he = fmaxf(ey2 - ey, 0.f);
    float ae = we * he;
    return iou - (ae - uni) / ae;
}

__global__ void final_kernel(const float* __restrict__ logits,
                             const float* __restrict__ pboxes,
                             const float* __restrict__ tboxes,
                             const int* __restrict__ tids,
                             float* __restrict__ out) {
    int n = blockIdx.x;
    int t = threadIdx.x;
    if (t >= T) return;

    float a = g_ab[(size_t)n * TPAD + t];
    float b = g_ab[(size_t)(640 + n) * TPAD + t];

    int id = tids[t];
    float L = logits[n * C + id];
    float p = 1.f / (1.f + expf(-L));
    float pos_cc = 0.25f * (1.f - p) * (1.f - p) * (-logf(p + 1e-8f));
    float neg_cc = 0.75f * p * p * (-logf(1.f - p + 1e-8f));
    float cc = pos_cc - neg_cc;

    float4 pbx = reinterpret_cast<const float4*>(pboxes)[n];
    float4 tbx = reinterpret_cast<const float4*>(tboxes)[t];
    float cb = fabsf(pbx.x - tbx.x) + fabsf(pbx.y - tbx.y) +
               fabsf(pbx.z - tbx.z) + fabsf(pbx.w - tbx.w);

    float cg = -giou(cxcywh_to_xyxy(pbx), cxcywh_to_xyxy(tbx));

    float4 pm4 = make_float4(g_pstats[n * 8 + 0], g_pstats[n * 8 + 1],
                             g_pstats[n * 8 + 2], g_pstats[n * 8 + 3]);
    float4 tm4 = make_float4(g_tstats[t * 8 + 0], g_tstats[t * 8 + 1],
                             g_tstats[t * 8 + 2], g_tstats[t * 8 + 3]);
    float cgm = -giou(cxcywh_to_xyxy(pm4), cxcywh_to_xyxy(tm4));

    float psum = g_pstats[n * 8 + 4];
    float nsum = g_pstats[n * 8 + 5];
    float tsum = g_tstats[t * 8 + 4];
    float dice = 1.f - (2.f * a + 1e-5f) / (psum + tsum + 1e-5f);
    float foc = (b + nsum) * (1.f / 65536.f);

    out[n * T + t] = cb + cc + cg + cgm + dice + foc;
}

// ---------------- launch ------------------------------------------------------
extern "C" void kernel_launch(void* const* d_in, const int* in_sizes, int n_in,
                              void* d_out, int out_size) {
    const float* pred_logits = (const float*)d_in[0];
    const float* pred_boxes  = (const float*)d_in[1];
    const float* pred_masks  = (const float*)d_in[2];
    const float* tgt_boxes   = (const float*)d_in[3];
    const int*   tgt_ids     = (const int*)d_in[4];
    const int*   tgt_masks   = (const int*)d_in[5];
    float* out = (float*)d_out;

    cudaFuncSetAttribute(fused_kernel,
                         cudaFuncAttributeMaxDynamicSharedMemorySize, FUSED_SMEM);

    tgt_kernel<<<dim3(T, TSEG), 256>>>(tgt_masks);
    fused_kernel<<<dim3(10, KSLICES), 256, FUSED_SMEM>>>(pred_masks);
    reduce_all<<<403, 256>>>();
    final_kernel<<<NPRED, 64>>>(pred_logits, pred_boxes, tgt_boxes, tgt_ids, out);
}